// round 4
// baseline (speedup 1.0000x reference)
#include <cuda_runtime.h>
#include <math.h>

#define IH 512
#define IW 512
#define NB 32
#define TX 64
#define TY 32
#define MEAN_H 40
#define MEAN_S 76
#define MAG_H 36
#define MAG_S 72

typedef unsigned long long u64;

__device__ float d_G3[9], d_SX[9], d_SY[9];
__device__ float d_NM[81];     // border helper: NM[v][s] = sum_k nms_k[v]*dir_k[s]
__device__ u64   d_PGx[25];    // (Gx5,Gx5) broadcast pairs
__device__ u64   d_PGy[25];    // (Gy5,Gy5)
__device__ u64   d_PT5[25];    // (T5,T5)

__device__ __forceinline__ u64 pack2(float lo, float hi) {
    u64 d; asm("mov.b64 %0, {%1,%2};" : "=l"(d) : "f"(lo), "f"(hi)); return d;
}
__device__ __forceinline__ void unpack2(u64 v, float& lo, float& hi) {
    asm("mov.b64 {%0,%1}, %2;" : "=f"(lo), "=f"(hi) : "l"(v));
}
__device__ __forceinline__ float lo32(u64 v) {
    float f; asm("{ .reg .b32 t; mov.b64 {%0, t}, %1; }" : "=f"(f) : "l"(v)); return f;
}
__device__ __forceinline__ float hi32(u64 v) {
    float f; asm("{ .reg .b32 t; mov.b64 {t, %0}, %1; }" : "=f"(f) : "l"(v)); return f;
}
__device__ __forceinline__ u64 fma2(u64 a, u64 b, u64 c) {
    u64 d; asm("fma.rn.f32x2 %0, %1, %2, %3;" : "=l"(d) : "l"(a), "l"(b), "l"(c)); return d;
}
__device__ __forceinline__ u64 mul2(u64 a, u64 b) {
    u64 d; asm("mul.rn.f32x2 %0, %1, %2;" : "=l"(d) : "l"(a), "l"(b)); return d;
}

__global__ void prep_weights(const float* __restrict__ g,
                             const float* __restrict__ sx,
                             const float* __restrict__ sy,
                             const float* __restrict__ dirw,
                             const float* __restrict__ nmsw) {
    int t = threadIdx.x;
    if (t < 9) { d_G3[t] = g[t]; d_SX[t] = sx[t]; d_SY[t] = sy[t]; }
    if (t < 25) {
        int wy = t / 5 - 2, wx = t % 5 - 2;
        float ax = 0.f, ay = 0.f, tc = 0.f;
        for (int uy = -1; uy <= 1; ++uy)
            for (int ux = -1; ux <= 1; ++ux) {
                int vy = wy - uy, vx = wx - ux;
                if (vy < -1 || vy > 1 || vx < -1 || vx > 1) continue;
                int ui = (uy + 1) * 3 + (ux + 1);
                int vi = (vy + 1) * 3 + (vx + 1);
                ax += g[ui] * sx[vi];
                ay += g[ui] * sy[vi];
                for (int k = 0; k < 8; ++k)
                    tc += dirw[k * 9 + ui] * nmsw[k * 9 + vi];
            }
        d_PGx[t] = pack2(ax, ax);
        d_PGy[t] = pack2(ay, ay);
        d_PT5[t] = pack2(tc, tc);
    }
    if (t < 81) {
        int v = t / 9, s = t % 9;
        float a = 0.f;
        for (int k = 0; k < 8; ++k) a += nmsw[k * 9 + v] * dirw[k * 9 + s];
        d_NM[t] = a;
    }
}

__global__ __launch_bounds__(256) void canny_fused(const float* __restrict__ img,
                                                   float* __restrict__ out) {
    __shared__ __align__(16) float s_mean[MEAN_H][MEAN_S];
    __shared__ __align__(16) float s_mag[MAG_H][MAG_S];
    __shared__ u64 sPGx[25], sPGy[25], sPT[25];
    __shared__ float sNM[81], sG[9], sSX[9], sSY[9];

    const int tid = threadIdx.x;
    if (tid < 25) { sPGx[tid] = d_PGx[tid]; sPGy[tid] = d_PGy[tid]; sPT[tid] = d_PT5[tid]; }
    if (tid < 81) sNM[tid] = d_NM[tid];
    if (tid < 9)  { sG[tid] = d_G3[tid]; sSX[tid] = d_SX[tid]; sSY[tid] = d_SY[tid]; }

    const int b   = blockIdx.z;
    const int ty0 = blockIdx.y * TY;
    const int tx0 = blockIdx.x * TX;
    const float* im = img + (size_t)b * 3 * IH * IW;
    const bool edge = (blockIdx.x == 0) | (blockIdx.x == gridDim.x - 1) |
                      (blockIdx.y == 0) | (blockIdx.y == gridDim.y - 1);

    // ---- Phase 1: channel-mean tile (float4 groups, 18 x 40) ----
    for (int t = tid; t < 18 * MEAN_H; t += 256) {
        int r = t / 18, xg = t % 18;
        int gy = ty0 - 4 + r, gx = tx0 - 4 + 4 * xg;
        float4 v;
        if (!edge || (gy >= 0 && gy < IH && gx >= 0 && gx + 3 < IW)) {
            const float* p = im + gy * IW + gx;
            float4 a  = *(const float4*)p;
            float4 c1 = *(const float4*)(p + IH * IW);
            float4 c2 = *(const float4*)(p + 2 * IH * IW);
            v.x = (a.x + c1.x + c2.x) * (1.0f / 3.0f);
            v.y = (a.y + c1.y + c2.y) * (1.0f / 3.0f);
            v.z = (a.z + c1.z + c2.z) * (1.0f / 3.0f);
            v.w = (a.w + c1.w + c2.w) * (1.0f / 3.0f);
        } else {
            float tmp[4];
#pragma unroll
            for (int j = 0; j < 4; ++j) {
                int gxx = gx + j;
                float val = 0.f;
                if (gy >= 0 && gy < IH && gxx >= 0 && gxx < IW) {
                    int off = gy * IW + gxx;
                    val = (im[off] + im[IH * IW + off] + im[2 * IH * IW + off]) * (1.0f / 3.0f);
                }
                tmp[j] = val;
            }
            v = make_float4(tmp[0], tmp[1], tmp[2], tmp[3]);
        }
        *(float4*)&s_mean[r][4 * xg] = v;
    }
    __syncthreads();

    // ---- Phase 2: grad magnitude, rolling 5-row window, R=4 rows/thread ----
    // tasks: 17 x-groups (4-wide) x 9 row-strips = 153
    if (tid < 153) {
        const int xg = tid % 17, st = tid / 17;
        const int i0 = 4 * xg;
        const int base = 4 * st;
        u64 win[5][4];
#pragma unroll
        for (int r = 0; r < 8; ++r) {
            const ulonglong2* rp = (const ulonglong2*)&s_mean[base + r][i0];
            ulonglong2 q0 = rp[0], q1 = rp[1];
            win[r % 5][0] = q0.x; win[r % 5][1] = q0.y;
            win[r % 5][2] = q1.x; win[r % 5][3] = q1.y;
            if (r >= 4) {
                const int ly = base + r - 4;  // mag row
                u64 gx01 = 0, gx23 = 0, gy01 = 0, gy23 = 0;
#pragma unroll
                for (int wy = 0; wy < 5; ++wy) {
                    const u64* e = win[(r - 4 + wy) % 5];
                    u64 o1 = pack2(hi32(e[0]), lo32(e[1]));
                    u64 o3 = pack2(hi32(e[1]), lo32(e[2]));
                    u64 o5 = pack2(hi32(e[2]), lo32(e[3]));
                    u64 pr[7] = { e[0], o1, e[1], o3, e[2], o5, e[3] };
#pragma unroll
                    for (int k = 0; k < 5; ++k) {
                        u64 wx = sPGx[wy * 5 + k], wyw = sPGy[wy * 5 + k];
                        gx01 = fma2(wx,  pr[k],     gx01);
                        gx23 = fma2(wx,  pr[k + 2], gx23);
                        gy01 = fma2(wyw, pr[k],     gy01);
                        gy23 = fma2(wyw, pr[k + 2], gy23);
                    }
                }
                u64 s01 = fma2(gx01, gx01, mul2(gy01, gy01));
                u64 s23 = fma2(gx23, gx23, mul2(gy23, gy23));
                float m[4];
                m[0] = sqrtf(lo32(s01)); m[1] = sqrtf(hi32(s01));
                m[2] = sqrtf(lo32(s23)); m[3] = sqrtf(hi32(s23));
                if (edge) {
                    int gy = ty0 - 2 + ly, gxb = tx0 - 2 + i0;
#pragma unroll
                    for (int j = 0; j < 4; ++j) {
                        int gxx = gxb + j;
                        if (gy < 0 || gy >= IH || gxx < 0 || gxx >= IW) {
                            m[j] = 0.f;
                        } else if (gy < 1 || gy > IH - 2 || gxx < 1 || gxx > IW - 2) {
                            float ax = 0.f, ay = 0.f;
                            for (int uy = 0; uy < 3; ++uy)
                                for (int ux = 0; ux < 3; ++ux) {
                                    int ry = gy + uy - 1, rx = gxx + ux - 1;
                                    if (ry < 0 || ry >= IH || rx < 0 || rx >= IW) continue;
                                    float bl = 0.f;
                                    for (int vy = 0; vy < 3; ++vy)
                                        for (int vx = 0; vx < 3; ++vx)
                                            bl = fmaf(sG[vy * 3 + vx],
                                                      s_mean[ly + uy + vy][i0 + j + ux + vx], bl);
                                    ax = fmaf(sSX[uy * 3 + ux], bl, ax);
                                    ay = fmaf(sSY[uy * 3 + ux], bl, ay);
                                }
                            m[j] = sqrtf(ax * ax + ay * ay);
                        }
                    }
                }
                *(float4*)&s_mag[ly][i0] = make_float4(m[0], m[1], m[2], m[3]);
            }
        }
    }
    __syncthreads();

    // ---- Phase 3: thin edges, rolling window, R=2 rows/thread ----
    // tasks: 16 x-groups x 16 row-strips = 256
    {
        const int xg = tid % 16, st = tid / 16;
        const int c0 = 4 * xg;
        const int base = 2 * st;
        float* ob = out + (size_t)b * IH * IW;
        u64 win[5][4];
#pragma unroll
        for (int r = 0; r < 6; ++r) {
            const ulonglong2* rp = (const ulonglong2*)&s_mag[base + r][c0];
            ulonglong2 q0 = rp[0], q1 = rp[1];
            win[r % 5][0] = q0.x; win[r % 5][1] = q0.y;
            win[r % 5][2] = q1.x; win[r % 5][3] = q1.y;
            if (r >= 4) {
                const int ro = base + r - 4;  // output row within tile
                u64 a01 = 0, a23 = 0;
#pragma unroll
                for (int wy = 0; wy < 5; ++wy) {
                    const u64* e = win[(r - 4 + wy) % 5];
                    u64 o1 = pack2(hi32(e[0]), lo32(e[1]));
                    u64 o3 = pack2(hi32(e[1]), lo32(e[2]));
                    u64 o5 = pack2(hi32(e[2]), lo32(e[3]));
                    u64 pr[7] = { e[0], o1, e[1], o3, e[2], o5, e[3] };
#pragma unroll
                    for (int k = 0; k < 5; ++k) {
                        u64 w = sPT[wy * 5 + k];
                        a01 = fma2(w, pr[k],     a01);
                        a23 = fma2(w, pr[k + 2], a23);
                    }
                }
                float o[4];
                o[0] = lo32(a01); o[1] = hi32(a01);
                o[2] = lo32(a23); o[3] = hi32(a23);
                int gy = ty0 + ro, gx = tx0 + c0;
                if (edge) {
#pragma unroll
                    for (int j = 0; j < 4; ++j) {
                        int gxx = gx + j;
                        if (gy < 1 || gy > IH - 2 || gxx < 1 || gxx > IW - 2) {
                            float acc = 0.f;
                            for (int vy = 0; vy < 3; ++vy)
                                for (int vx = 0; vx < 3; ++vx) {
                                    int ry = gy + vy - 1, rx = gxx + vx - 1;
                                    if (ry < 0 || ry >= IH || rx < 0 || rx >= IW) continue;
                                    for (int sy = 0; sy < 3; ++sy)
                                        for (int sx2 = 0; sx2 < 3; ++sx2)
                                            acc = fmaf(sNM[(vy * 3 + vx) * 9 + sy * 3 + sx2],
                                                       s_mag[ro + vy + sy][c0 + j + vx + sx2], acc);
                                }
                            o[j] = acc;
                        }
                    }
                }
                *(float4*)&ob[gy * IW + gx] = make_float4(o[0], o[1], o[2], o[3]);
            }
        }
    }
}

extern "C" void kernel_launch(void* const* d_in, const int* in_sizes, int n_in,
                              void* d_out, int out_size) {
    const float* img   = (const float*)d_in[0];
    const float* gauss = (const float*)d_in[1];
    const float* sx    = (const float*)d_in[2];
    const float* sy    = (const float*)d_in[3];
    const float* dirw  = (const float*)d_in[4];
    const float* nmsw  = (const float*)d_in[5];
    float* out = (float*)d_out;

    prep_weights<<<1, 128>>>(gauss, sx, sy, dirw, nmsw);

    dim3 grid(IW / TX, IH / TY, NB);
    canny_fused<<<grid, 256>>>(img, out);
}

// round 6
// speedup vs baseline: 1.0607x; 1.0607x over previous
#include <cuda_runtime.h>
#include <math.h>

#define IH 512
#define IW 512
#define NB 32
#define TX 64
#define TY 32
#define MEAN_H 40
#define MEAN_S 76
#define MAG_H 36
#define MAG_S 72

typedef unsigned long long u64;

__device__ float d_G3[9], d_SX[9], d_SY[9];
__device__ float d_NM[81];     // border helper: NM[v][s] = sum_k nms_k[v]*dir_k[s]
__device__ u64   d_PGx[25];    // (Gx5,Gx5) broadcast pairs
__device__ u64   d_PGy[25];    // (Gy5,Gy5)
__device__ u64   d_PT5[25];    // (T5,T5)

__device__ __forceinline__ u64 pack2(float lo, float hi) {
    u64 d; asm("mov.b64 %0, {%1,%2};" : "=l"(d) : "f"(lo), "f"(hi)); return d;
}
__device__ __forceinline__ float lo32(u64 v) {
    float f; asm("{ .reg .b32 t; mov.b64 {%0, t}, %1; }" : "=f"(f) : "l"(v)); return f;
}
__device__ __forceinline__ float hi32(u64 v) {
    float f; asm("{ .reg .b32 t; mov.b64 {t, %0}, %1; }" : "=f"(f) : "l"(v)); return f;
}
__device__ __forceinline__ u64 fma2(u64 a, u64 b, u64 c) {
    u64 d; asm("fma.rn.f32x2 %0, %1, %2, %3;" : "=l"(d) : "l"(a), "l"(b), "l"(c)); return d;
}
__device__ __forceinline__ u64 mul2(u64 a, u64 b) {
    u64 d; asm("mul.rn.f32x2 %0, %1, %2;" : "=l"(d) : "l"(a), "l"(b)); return d;
}

__global__ void prep_weights(const float* __restrict__ g,
                             const float* __restrict__ sx,
                             const float* __restrict__ sy,
                             const float* __restrict__ dirw,
                             const float* __restrict__ nmsw) {
    int t = threadIdx.x;
    if (t < 9) { d_G3[t] = g[t]; d_SX[t] = sx[t]; d_SY[t] = sy[t]; }
    if (t < 25) {
        int wy = t / 5 - 2, wx = t % 5 - 2;
        float ax = 0.f, ay = 0.f, tc = 0.f;
        for (int uy = -1; uy <= 1; ++uy)
            for (int ux = -1; ux <= 1; ++ux) {
                int vy = wy - uy, vx = wx - ux;
                if (vy < -1 || vy > 1 || vx < -1 || vx > 1) continue;
                int ui = (uy + 1) * 3 + (ux + 1);
                int vi = (vy + 1) * 3 + (vx + 1);
                ax += g[ui] * sx[vi];
                ay += g[ui] * sy[vi];
                for (int k = 0; k < 8; ++k)
                    tc += dirw[k * 9 + ui] * nmsw[k * 9 + vi];
            }
        d_PGx[t] = pack2(ax, ax);
        d_PGy[t] = pack2(ay, ay);
        d_PT5[t] = pack2(tc, tc);
    }
    if (t < 81) {
        int v = t / 9, s = t % 9;
        float a = 0.f;
        for (int k = 0; k < 8; ++k) a += nmsw[k * 9 + v] * dirw[k * 9 + s];
        d_NM[t] = a;
    }
}

__global__ __launch_bounds__(256) void canny_fused(const float* __restrict__ img,
                                                   float* __restrict__ out) {
    __shared__ __align__(16) float s_mean[MEAN_H][MEAN_S];
    __shared__ __align__(16) float s_mag[MAG_H][MAG_S];
    __shared__ u64 sPGx[25], sPGy[25], sPT[25];
    __shared__ float sNM[81], sG[9], sSX[9], sSY[9];

    const int tid = threadIdx.x;
    if (tid < 25) { sPGx[tid] = d_PGx[tid]; sPGy[tid] = d_PGy[tid]; sPT[tid] = d_PT5[tid]; }
    if (tid < 81) sNM[tid] = d_NM[tid];
    if (tid < 9)  { sG[tid] = d_G3[tid]; sSX[tid] = d_SX[tid]; sSY[tid] = d_SY[tid]; }

    const int b   = blockIdx.z;
    const int ty0 = blockIdx.y * TY;
    const int tx0 = blockIdx.x * TX;
    const float* im = img + (size_t)b * 3 * IH * IW;
    const bool edge = (blockIdx.x == 0) | (blockIdx.x == gridDim.x - 1) |
                      (blockIdx.y == 0) | (blockIdx.y == gridDim.y - 1);

    // ---- Phase 1: channel-mean tile (float4 groups, 18 x 40) ----
    for (int t = tid; t < 18 * MEAN_H; t += 256) {
        int r = t / 18, xg = t % 18;
        int gy = ty0 - 4 + r, gx = tx0 - 4 + 4 * xg;
        float4 v;
        if (!edge || (gy >= 0 && gy < IH && gx >= 0 && gx + 3 < IW)) {
            const float* p = im + gy * IW + gx;
            float4 a  = *(const float4*)p;
            float4 c1 = *(const float4*)(p + IH * IW);
            float4 c2 = *(const float4*)(p + 2 * IH * IW);
            v.x = (a.x + c1.x + c2.x) * (1.0f / 3.0f);
            v.y = (a.y + c1.y + c2.y) * (1.0f / 3.0f);
            v.z = (a.z + c1.z + c2.z) * (1.0f / 3.0f);
            v.w = (a.w + c1.w + c2.w) * (1.0f / 3.0f);
        } else {
            float tmp[4];
#pragma unroll
            for (int j = 0; j < 4; ++j) {
                int gxx = gx + j;
                float val = 0.f;
                if (gy >= 0 && gy < IH && gxx >= 0 && gxx < IW) {
                    int off = gy * IW + gxx;
                    val = (im[off] + im[IH * IW + off] + im[2 * IH * IW + off]) * (1.0f / 3.0f);
                }
                tmp[j] = val;
            }
            v = make_float4(tmp[0], tmp[1], tmp[2], tmp[3]);
        }
        *(float4*)&s_mean[r][4 * xg] = v;
    }
    __syncthreads();

    // ---- Phase 2: grad magnitude, pixel-pair FFMA2, 4-wide tasks ----
    for (int t = tid; t < 17 * MAG_H; t += 256) {
        int ly = t / 17, xg = t % 17, i0 = 4 * xg;
        u64 gx01 = 0, gx23 = 0, gy01 = 0, gy23 = 0;
#pragma unroll
        for (int wy = 0; wy < 5; ++wy) {
            const ulonglong2* rp = (const ulonglong2*)&s_mean[ly + wy][i0];
            ulonglong2 q0 = rp[0], q1 = rp[1];
            u64 e0 = q0.x, e1 = q0.y, e2 = q1.x, e3 = q1.y;
            u64 o1 = pack2(hi32(e0), lo32(e1));
            u64 o3 = pack2(hi32(e1), lo32(e2));
            u64 o5 = pack2(hi32(e2), lo32(e3));
            u64 pr[7] = { e0, o1, e1, o3, e2, o5, e3 };
#pragma unroll
            for (int k = 0; k < 5; ++k) {
                u64 wx = sPGx[wy * 5 + k], wyw = sPGy[wy * 5 + k];
                gx01 = fma2(wx,  pr[k],     gx01);
                gx23 = fma2(wx,  pr[k + 2], gx23);
                gy01 = fma2(wyw, pr[k],     gy01);
                gy23 = fma2(wyw, pr[k + 2], gy23);
            }
        }
        u64 s01 = fma2(gx01, gx01, mul2(gy01, gy01));
        u64 s23 = fma2(gx23, gx23, mul2(gy23, gy23));
        float m[4];
        m[0] = sqrtf(lo32(s01)); m[1] = sqrtf(hi32(s01));
        m[2] = sqrtf(lo32(s23)); m[3] = sqrtf(hi32(s23));
        if (edge) {
            int gy = ty0 - 2 + ly, gxb = tx0 - 2 + i0;
#pragma unroll
            for (int j = 0; j < 4; ++j) {
                int gxx = gxb + j;
                if (gy < 0 || gy >= IH || gxx < 0 || gxx >= IW) {
                    m[j] = 0.f;
                } else if (gy < 1 || gy > IH - 2 || gxx < 1 || gxx > IW - 2) {
                    float ax = 0.f, ay = 0.f;
                    for (int uy = 0; uy < 3; ++uy)
                        for (int ux = 0; ux < 3; ++ux) {
                            int ry = gy + uy - 1, rx = gxx + ux - 1;
                            if (ry < 0 || ry >= IH || rx < 0 || rx >= IW) continue;
                            float bl = 0.f;
                            for (int vy = 0; vy < 3; ++vy)
                                for (int vx = 0; vx < 3; ++vx)
                                    bl = fmaf(sG[vy * 3 + vx],
                                              s_mean[ly + uy + vy][i0 + j + ux + vx], bl);
                            ax = fmaf(sSX[uy * 3 + ux], bl, ax);
                            ay = fmaf(sSY[uy * 3 + ux], bl, ay);
                        }
                    m[j] = sqrtf(ax * ax + ay * ay);
                }
            }
        }
        *(float4*)&s_mag[ly][i0] = make_float4(m[0], m[1], m[2], m[3]);
    }
    __syncthreads();

    // ---- Phase 3: thin edges, pixel-pair FFMA2, 4-wide tasks ----
    float* ob = out + (size_t)b * IH * IW;
#pragma unroll
    for (int s = 0; s < 2; ++s) {
        int t = tid + s * 256;
        int row = t >> 4, xg = t & 15, c0 = 4 * xg;
        u64 a01 = 0, a23 = 0;
#pragma unroll
        for (int wy = 0; wy < 5; ++wy) {
            const ulonglong2* rp = (const ulonglong2*)&s_mag[row + wy][c0];
            ulonglong2 q0 = rp[0], q1 = rp[1];
            u64 e0 = q0.x, e1 = q0.y, e2 = q1.x, e3 = q1.y;
            u64 o1 = pack2(hi32(e0), lo32(e1));
            u64 o3 = pack2(hi32(e1), lo32(e2));
            u64 o5 = pack2(hi32(e2), lo32(e3));
            u64 pr[7] = { e0, o1, e1, o3, e2, o5, e3 };
#pragma unroll
            for (int k = 0; k < 5; ++k) {
                u64 w = sPT[wy * 5 + k];
                a01 = fma2(w, pr[k],     a01);
                a23 = fma2(w, pr[k + 2], a23);
            }
        }
        float o[4];
        o[0] = lo32(a01); o[1] = hi32(a01);
        o[2] = lo32(a23); o[3] = hi32(a23);
        int gy = ty0 + row, gx = tx0 + c0;
        if (edge) {
#pragma unroll
            for (int j = 0; j < 4; ++j) {
                int gxx = gx + j;
                if (gy < 1 || gy > IH - 2 || gxx < 1 || gxx > IW - 2) {
                    float acc = 0.f;
                    for (int vy = 0; vy < 3; ++vy)
                        for (int vx = 0; vx < 3; ++vx) {
                            int ry = gy + vy - 1, rx = gxx + vx - 1;
                            if (ry < 0 || ry >= IH || rx < 0 || rx >= IW) continue;
                            for (int sy = 0; sy < 3; ++sy)
                                for (int sx2 = 0; sx2 < 3; ++sx2)
                                    acc = fmaf(sNM[(vy * 3 + vx) * 9 + sy * 3 + sx2],
                                               s_mag[row + vy + sy][c0 + j + vx + sx2], acc);
                        }
                    o[j] = acc;
                }
            }
        }
        *(float4*)&ob[gy * IW + gx] = make_float4(o[0], o[1], o[2], o[3]);
    }
}

extern "C" void kernel_launch(void* const* d_in, const int* in_sizes, int n_in,
                              void* d_out, int out_size) {
    const float* img   = (const float*)d_in[0];
    const float* gauss = (const float*)d_in[1];
    const float* sx    = (const float*)d_in[2];
    const float* sy    = (const float*)d_in[3];
    const float* dirw  = (const float*)d_in[4];
    const float* nmsw  = (const float*)d_in[5];
    float* out = (float*)d_out;

    prep_weights<<<1, 128>>>(gauss, sx, sy, dirw, nmsw);

    dim3 grid(IW / TX, IH / TY, NB);
    canny_fused<<<grid, 256>>>(img, out);
}

// round 8
// speedup vs baseline: 2.2593x; 2.1300x over previous
#include <cuda_runtime.h>
#include <math.h>

#define IH 512
#define IW 512
#define NB 32
#define TX 64
#define TY 32
#define MEAN_H 40
#define MEAN_S 76
#define MAG_H 36
#define MAG_S 72

// weights prepared per launch (they are runtime inputs)
__device__ float d_G3[9], d_SX[9], d_SY[9];
__device__ float d_Gx5[25];   // gauss∘sobel_x composed 5x5
__device__ float d_Gy5[25];   // gauss∘sobel_y composed 5x5
__device__ float d_T5[25];    // dir∘nms composed 5x5
__device__ float d_NM[81];    // border helper: NM[v][s] = sum_k nms_k[v]*dir_k[s]

__device__ __forceinline__ float fsqrt_fast(float x) {
    float r; asm("sqrt.approx.f32 %0, %1;" : "=f"(r) : "f"(x)); return r;
}

__global__ void prep_weights(const float* __restrict__ g,
                             const float* __restrict__ sx,
                             const float* __restrict__ sy,
                             const float* __restrict__ dirw,
                             const float* __restrict__ nmsw) {
    int t = threadIdx.x;
    if (t < 9) { d_G3[t] = g[t]; d_SX[t] = sx[t]; d_SY[t] = sy[t]; }
    if (t < 25) {
        int wy = t / 5 - 2, wx = t % 5 - 2;
        float ax = 0.f, ay = 0.f, tc = 0.f;
        for (int uy = -1; uy <= 1; ++uy)
            for (int ux = -1; ux <= 1; ++ux) {
                int vy = wy - uy, vx = wx - ux;
                if (vy < -1 || vy > 1 || vx < -1 || vx > 1) continue;
                int ui = (uy + 1) * 3 + (ux + 1);
                int vi = (vy + 1) * 3 + (vx + 1);
                ax += g[ui] * sx[vi];
                ay += g[ui] * sy[vi];
                for (int k = 0; k < 8; ++k)
                    tc += dirw[k * 9 + ui] * nmsw[k * 9 + vi];
            }
        d_Gx5[t] = ax; d_Gy5[t] = ay; d_T5[t] = tc;
    }
    if (t < 81) {
        int v = t / 9, s = t % 9;
        float a = 0.f;
        for (int k = 0; k < 8; ++k) a += nmsw[k * 9 + v] * dirw[k * 9 + s];
        d_NM[t] = a;
    }
}

__global__ __launch_bounds__(256, 4) void canny_fused(const float* __restrict__ img,
                                                      float* __restrict__ out) {
    __shared__ __align__(16) float s_mean[MEAN_H][MEAN_S];
    __shared__ __align__(16) float s_mag[MAG_H][MAG_S];
    __shared__ float sGx[25], sGy[25], sT5[25], sNM[81], sG[9], sSX[9], sSY[9];

    const int tid = threadIdx.x;
    if (tid < 25) { sGx[tid] = d_Gx5[tid]; sGy[tid] = d_Gy5[tid]; sT5[tid] = d_T5[tid]; }
    if (tid < 81) sNM[tid] = d_NM[tid];
    if (tid < 9)  { sG[tid] = d_G3[tid]; sSX[tid] = d_SX[tid]; sSY[tid] = d_SY[tid]; }

    const int b   = blockIdx.z;
    const int ty0 = blockIdx.y * TY;
    const int tx0 = blockIdx.x * TX;
    const float* im = img + (size_t)b * 3 * IH * IW;
    const bool edge = (blockIdx.x == 0) | (blockIdx.x == gridDim.x - 1) |
                      (blockIdx.y == 0) | (blockIdx.y == gridDim.y - 1);

    // ---- Phase 1: channel-mean tile, float4 groups (18 groups x 40 rows) ----
    for (int t = tid; t < 18 * MEAN_H; t += 256) {
        int r = t / 18, xg = t % 18;
        int gy = ty0 - 4 + r, gx = tx0 - 4 + 4 * xg;
        float4 v;
        if (!edge || (gy >= 0 && gy < IH && gx >= 0 && gx + 3 < IW)) {
            const float* p = im + gy * IW + gx;
            float4 a  = *(const float4*)p;
            float4 c1 = *(const float4*)(p + IH * IW);
            float4 c2 = *(const float4*)(p + 2 * IH * IW);
            v.x = (a.x + c1.x + c2.x) * (1.0f / 3.0f);
            v.y = (a.y + c1.y + c2.y) * (1.0f / 3.0f);
            v.z = (a.z + c1.z + c2.z) * (1.0f / 3.0f);
            v.w = (a.w + c1.w + c2.w) * (1.0f / 3.0f);
        } else {
            float tmp[4];
#pragma unroll
            for (int j = 0; j < 4; ++j) {
                int gxx = gx + j;
                float val = 0.f;
                if (gy >= 0 && gy < IH && gxx >= 0 && gxx < IW) {
                    int off = gy * IW + gxx;
                    val = (im[off] + im[IH * IW + off] + im[2 * IH * IW + off]) * (1.0f / 3.0f);
                }
                tmp[j] = val;
            }
            v = make_float4(tmp[0], tmp[1], tmp[2], tmp[3]);
        }
        *(float4*)&s_mean[r][4 * xg] = v;
    }
    __syncthreads();

    // ---- Phase 2: grad magnitude, 4-wide tasks, scalar FFMA ----
    for (int t = tid; t < 17 * MAG_H; t += 256) {
        int ly = t / 17, xg = t % 17, i0 = 4 * xg;
        float gxa[4] = {0.f, 0.f, 0.f, 0.f};
        float gya[4] = {0.f, 0.f, 0.f, 0.f};
#pragma unroll
        for (int wy = 0; wy < 5; ++wy) {
            const float* rp = &s_mean[ly + wy][i0];
            float4 a = *(const float4*)rp;
            float4 bq = *(const float4*)(rp + 4);
            float v[8] = {a.x, a.y, a.z, a.w, bq.x, bq.y, bq.z, bq.w};
#pragma unroll
            for (int j = 0; j < 4; ++j)
#pragma unroll
                for (int k = 0; k < 5; ++k) {
                    gxa[j] = fmaf(sGx[wy * 5 + k], v[j + k], gxa[j]);
                    gya[j] = fmaf(sGy[wy * 5 + k], v[j + k], gya[j]);
                }
        }
        float m[4];
#pragma unroll
        for (int j = 0; j < 4; ++j)
            m[j] = fsqrt_fast(fmaf(gxa[j], gxa[j], gya[j] * gya[j]));
        if (edge) {
            int gy = ty0 - 2 + ly, gxb = tx0 - 2 + i0;
#pragma unroll
            for (int j = 0; j < 4; ++j) {
                int gxx = gxb + j;
                if (gy < 0 || gy >= IH || gxx < 0 || gxx >= IW) {
                    m[j] = 0.f;
                } else if (gy < 1 || gy > IH - 2 || gxx < 1 || gxx > IW - 2) {
                    float ax = 0.f, ay = 0.f;
                    for (int uy = 0; uy < 3; ++uy)
                        for (int ux = 0; ux < 3; ++ux) {
                            int ry = gy + uy - 1, rx = gxx + ux - 1;
                            if (ry < 0 || ry >= IH || rx < 0 || rx >= IW) continue;
                            float bl = 0.f;
                            for (int vy = 0; vy < 3; ++vy)
                                for (int vx = 0; vx < 3; ++vx)
                                    bl = fmaf(sG[vy * 3 + vx],
                                              s_mean[ly + uy + vy][i0 + j + ux + vx], bl);
                            ax = fmaf(sSX[uy * 3 + ux], bl, ax);
                            ay = fmaf(sSY[uy * 3 + ux], bl, ay);
                        }
                    m[j] = fsqrt_fast(fmaf(ax, ax, ay * ay));
                }
            }
        }
        *(float4*)&s_mag[ly][i0] = make_float4(m[0], m[1], m[2], m[3]);
    }
    __syncthreads();

    // ---- Phase 3: thin edges, 4-wide tasks, scalar FFMA composed 5x5 ----
    float* ob = out + (size_t)b * IH * IW;
#pragma unroll
    for (int s = 0; s < 2; ++s) {
        int t = tid + s * 256;
        int row = t >> 4, xg = t & 15, c0 = 4 * xg;
        float o[4] = {0.f, 0.f, 0.f, 0.f};
#pragma unroll
        for (int wy = 0; wy < 5; ++wy) {
            const float* rp = &s_mag[row + wy][c0];
            float4 a = *(const float4*)rp;
            float4 bq = *(const float4*)(rp + 4);
            float v[8] = {a.x, a.y, a.z, a.w, bq.x, bq.y, bq.z, bq.w};
#pragma unroll
            for (int j = 0; j < 4; ++j)
#pragma unroll
                for (int k = 0; k < 5; ++k)
                    o[j] = fmaf(sT5[wy * 5 + k], v[j + k], o[j]);
        }
        int gy = ty0 + row, gx = tx0 + c0;
        if (edge) {
#pragma unroll
            for (int j = 0; j < 4; ++j) {
                int gxx = gx + j;
                if (gy < 1 || gy > IH - 2 || gxx < 1 || gxx > IW - 2) {
                    float acc = 0.f;
                    for (int vy = 0; vy < 3; ++vy)
                        for (int vx = 0; vx < 3; ++vx) {
                            int ry = gy + vy - 1, rx = gxx + vx - 1;
                            if (ry < 0 || ry >= IH || rx < 0 || rx >= IW) continue;
                            for (int sy = 0; sy < 3; ++sy)
                                for (int sx2 = 0; sx2 < 3; ++sx2)
                                    acc = fmaf(sNM[(vy * 3 + vx) * 9 + sy * 3 + sx2],
                                               s_mag[row + vy + sy][c0 + j + vx + sx2], acc);
                        }
                    o[j] = acc;
                }
            }
        }
        *(float4*)&ob[gy * IW + gx] = make_float4(o[0], o[1], o[2], o[3]);
    }
}

extern "C" void kernel_launch(void* const* d_in, const int* in_sizes, int n_in,
                              void* d_out, int out_size) {
    const float* img   = (const float*)d_in[0];
    const float* gauss = (const float*)d_in[1];
    const float* sx    = (const float*)d_in[2];
    const float* sy    = (const float*)d_in[3];
    const float* dirw  = (const float*)d_in[4];
    const float* nmsw  = (const float*)d_in[5];
    float* out = (float*)d_out;

    prep_weights<<<1, 128>>>(gauss, sx, sy, dirw, nmsw);

    dim3 grid(IW / TX, IH / TY, NB);
    canny_fused<<<grid, 256>>>(img, out);
}

// round 10
// speedup vs baseline: 2.4550x; 1.0866x over previous
#include <cuda_runtime.h>
#include <math.h>

#define IH 512
#define IW 512
#define NB 32
#define TX 64
#define TY 32
#define MEAN_H 40
#define MEAN_S 76
#define MAG_H 36
#define MAG_S 72

// weights prepared per launch (they are runtime inputs)
__device__ float d_G3[9], d_SX[9], d_SY[9];
__device__ float d_Gx5[25];   // gauss∘sobel_x composed 5x5
__device__ float d_Gy5[25];   // gauss∘sobel_y composed 5x5
__device__ float d_T5[25];    // dir∘nms composed 5x5
__device__ float d_NM[81];    // border helper: NM[v][s] = sum_k nms_k[v]*dir_k[s]

__device__ __forceinline__ float fsqrt_fast(float x) {
    float r; asm("sqrt.approx.f32 %0, %1;" : "=f"(r) : "f"(x)); return r;
}

__global__ void prep_weights(const float* __restrict__ g,
                             const float* __restrict__ sx,
                             const float* __restrict__ sy,
                             const float* __restrict__ dirw,
                             const float* __restrict__ nmsw) {
    int t = threadIdx.x;
    if (t < 9) { d_G3[t] = g[t]; d_SX[t] = sx[t]; d_SY[t] = sy[t]; }
    if (t < 25) {
        int wy = t / 5 - 2, wx = t % 5 - 2;
        float ax = 0.f, ay = 0.f, tc = 0.f;
        for (int uy = -1; uy <= 1; ++uy)
            for (int ux = -1; ux <= 1; ++ux) {
                int vy = wy - uy, vx = wx - ux;
                if (vy < -1 || vy > 1 || vx < -1 || vx > 1) continue;
                int ui = (uy + 1) * 3 + (ux + 1);
                int vi = (vy + 1) * 3 + (vx + 1);
                ax += g[ui] * sx[vi];
                ay += g[ui] * sy[vi];
                for (int k = 0; k < 8; ++k)
                    tc += dirw[k * 9 + ui] * nmsw[k * 9 + vi];
            }
        d_Gx5[t] = ax; d_Gy5[t] = ay; d_T5[t] = tc;
    }
    if (t < 81) {
        int v = t / 9, s = t % 9;
        float a = 0.f;
        for (int k = 0; k < 8; ++k) a += nmsw[k * 9 + v] * dirw[k * 9 + s];
        d_NM[t] = a;
    }
}

__global__ __launch_bounds__(256, 4) void canny_fused(const float* __restrict__ img,
                                                      float* __restrict__ out) {
    __shared__ __align__(16) float s_mean[MEAN_H][MEAN_S];
    __shared__ __align__(16) float s_mag[MAG_H][MAG_S];
    __shared__ float sGx[25], sGy[25], sT5[25], sNM[81], sG[9], sSX[9], sSY[9];

    const int tid = threadIdx.x;
    if (tid < 25) { sGx[tid] = d_Gx5[tid]; sGy[tid] = d_Gy5[tid]; sT5[tid] = d_T5[tid]; }
    if (tid < 81) sNM[tid] = d_NM[tid];
    if (tid < 9)  { sG[tid] = d_G3[tid]; sSX[tid] = d_SX[tid]; sSY[tid] = d_SY[tid]; }

    const int b   = blockIdx.z;
    const int ty0 = blockIdx.y * TY;
    const int tx0 = blockIdx.x * TX;
    const float* im = img + (size_t)b * 3 * IH * IW;
    const bool edge = (blockIdx.x == 0) | (blockIdx.x == gridDim.x - 1) |
                      (blockIdx.y == 0) | (blockIdx.y == gridDim.y - 1);

    // ---- Phase 1: channel-mean tile, float4 groups (18 groups x 40 rows) ----
    for (int t = tid; t < 18 * MEAN_H; t += 256) {
        int r = t / 18, xg = t % 18;
        int gy = ty0 - 4 + r, gx = tx0 - 4 + 4 * xg;
        float4 v;
        if (!edge || (gy >= 0 && gy < IH && gx >= 0 && gx + 3 < IW)) {
            const float* p = im + gy * IW + gx;
            float4 a  = *(const float4*)p;
            float4 c1 = *(const float4*)(p + IH * IW);
            float4 c2 = *(const float4*)(p + 2 * IH * IW);
            v.x = (a.x + c1.x + c2.x) * (1.0f / 3.0f);
            v.y = (a.y + c1.y + c2.y) * (1.0f / 3.0f);
            v.z = (a.z + c1.z + c2.z) * (1.0f / 3.0f);
            v.w = (a.w + c1.w + c2.w) * (1.0f / 3.0f);
        } else {
            float tmp[4];
#pragma unroll
            for (int j = 0; j < 4; ++j) {
                int gxx = gx + j;
                float val = 0.f;
                if (gy >= 0 && gy < IH && gxx >= 0 && gxx < IW) {
                    int off = gy * IW + gxx;
                    val = (im[off] + im[IH * IW + off] + im[2 * IH * IW + off]) * (1.0f / 3.0f);
                }
                tmp[j] = val;
            }
            v = make_float4(tmp[0], tmp[1], tmp[2], tmp[3]);
        }
        *(float4*)&s_mean[r][4 * xg] = v;
    }
    __syncthreads();

    // ---- Phase 2: grad magnitude, 3 rows/task, streamed rows ----
    // 12 strips x 17 x-groups = 204 tasks
    if (tid < 204) {
        const int xg = tid % 17, strip = tid / 17;
        const int i0 = 4 * xg;
        const int base = 3 * strip;
        float axc[3][4], ayc[3][4];
#pragma unroll
        for (int o = 0; o < 3; ++o)
#pragma unroll
            for (int j = 0; j < 4; ++j) { axc[o][j] = 0.f; ayc[o][j] = 0.f; }
#pragma unroll
        for (int r = 0; r < 7; ++r) {
            const float* rp = &s_mean[base + r][i0];
            float4 a = *(const float4*)rp;
            float4 bq = *(const float4*)(rp + 4);
            float v[8] = {a.x, a.y, a.z, a.w, bq.x, bq.y, bq.z, bq.w};
#pragma unroll
            for (int o = 0; o < 3; ++o) {
                const int wy = r - o;
                if (wy < 0 || wy > 4) continue;
#pragma unroll
                for (int j = 0; j < 4; ++j)
#pragma unroll
                    for (int k = 0; k < 5; ++k) {
                        axc[o][j] = fmaf(sGx[wy * 5 + k], v[j + k], axc[o][j]);
                        ayc[o][j] = fmaf(sGy[wy * 5 + k], v[j + k], ayc[o][j]);
                    }
            }
        }
#pragma unroll
        for (int o = 0; o < 3; ++o) {
            const int ly = base + o;
            float m[4];
#pragma unroll
            for (int j = 0; j < 4; ++j)
                m[j] = fsqrt_fast(fmaf(axc[o][j], axc[o][j], ayc[o][j] * ayc[o][j]));
            if (edge) {
                int gy = ty0 - 2 + ly, gxb = tx0 - 2 + i0;
#pragma unroll
                for (int j = 0; j < 4; ++j) {
                    int gxx = gxb + j;
                    if (gy < 0 || gy >= IH || gxx < 0 || gxx >= IW) {
                        m[j] = 0.f;
                    } else if (gy < 1 || gy > IH - 2 || gxx < 1 || gxx > IW - 2) {
                        float ax = 0.f, ay = 0.f;
                        for (int uy = 0; uy < 3; ++uy)
                            for (int ux = 0; ux < 3; ++ux) {
                                int ry = gy + uy - 1, rx = gxx + ux - 1;
                                if (ry < 0 || ry >= IH || rx < 0 || rx >= IW) continue;
                                float bl = 0.f;
                                for (int vy = 0; vy < 3; ++vy)
                                    for (int vx = 0; vx < 3; ++vx)
                                        bl = fmaf(sG[vy * 3 + vx],
                                                  s_mean[ly + uy + vy][i0 + j + ux + vx], bl);
                                ax = fmaf(sSX[uy * 3 + ux], bl, ax);
                                ay = fmaf(sSY[uy * 3 + ux], bl, ay);
                            }
                        m[j] = fsqrt_fast(fmaf(ax, ax, ay * ay));
                    }
                }
            }
            *(float4*)&s_mag[ly][i0] = make_float4(m[0], m[1], m[2], m[3]);
        }
    }
    __syncthreads();

    // ---- Phase 3: thin edges, 2 rows/task, streamed rows ----
    // 16 row-pairs x 16 x-groups = 256 tasks
    {
        const int xg = tid & 15, pair = tid >> 4;
        const int c0 = 4 * xg;
        const int base = 2 * pair;
        float* ob = out + (size_t)b * IH * IW;
        float o[2][4];
#pragma unroll
        for (int q = 0; q < 2; ++q)
#pragma unroll
            for (int j = 0; j < 4; ++j) o[q][j] = 0.f;
#pragma unroll
        for (int r = 0; r < 6; ++r) {
            const float* rp = &s_mag[base + r][c0];
            float4 a = *(const float4*)rp;
            float4 bq = *(const float4*)(rp + 4);
            float v[8] = {a.x, a.y, a.z, a.w, bq.x, bq.y, bq.z, bq.w};
#pragma unroll
            for (int q = 0; q < 2; ++q) {
                const int wy = r - q;
                if (wy < 0 || wy > 4) continue;
#pragma unroll
                for (int j = 0; j < 4; ++j)
#pragma unroll
                    for (int k = 0; k < 5; ++k)
                        o[q][j] = fmaf(sT5[wy * 5 + k], v[j + k], o[q][j]);
            }
        }
#pragma unroll
        for (int q = 0; q < 2; ++q) {
            const int row = base + q;
            int gy = ty0 + row, gx = tx0 + c0;
            float w[4] = {o[q][0], o[q][1], o[q][2], o[q][3]};
            if (edge) {
#pragma unroll
                for (int j = 0; j < 4; ++j) {
                    int gxx = gx + j;
                    if (gy < 1 || gy > IH - 2 || gxx < 1 || gxx > IW - 2) {
                        float acc = 0.f;
                        for (int vy = 0; vy < 3; ++vy)
                            for (int vx = 0; vx < 3; ++vx) {
                                int ry = gy + vy - 1, rx = gxx + vx - 1;
                                if (ry < 0 || ry >= IH || rx < 0 || rx >= IW) continue;
                                for (int sy = 0; sy < 3; ++sy)
                                    for (int sx2 = 0; sx2 < 3; ++sx2)
                                        acc = fmaf(sNM[(vy * 3 + vx) * 9 + sy * 3 + sx2],
                                                   s_mag[row + vy + sy][c0 + j + vx + sx2], acc);
                            }
                        w[j] = acc;
                    }
                }
            }
            *(float4*)&ob[gy * IW + gx] = make_float4(w[0], w[1], w[2], w[3]);
        }
    }
}

extern "C" void kernel_launch(void* const* d_in, const int* in_sizes, int n_in,
                              void* d_out, int out_size) {
    const float* img   = (const float*)d_in[0];
    const float* gauss = (const float*)d_in[1];
    const float* sx    = (const float*)d_in[2];
    const float* sy    = (const float*)d_in[3];
    const float* dirw  = (const float*)d_in[4];
    const float* nmsw  = (const float*)d_in[5];
    float* out = (float*)d_out;

    prep_weights<<<1, 128>>>(gauss, sx, sy, dirw, nmsw);

    dim3 grid(IW / TX, IH / TY, NB);
    canny_fused<<<grid, 256>>>(img, out);
}